// round 2
// baseline (speedup 1.0000x reference)
#include <cuda_runtime.h>

// Random_RNN two-hop sparse propagation — bucketized single-pass build.
//
// Hop1: acc1[j][b] = sum_{in-edges dst=j} w * x[b][src]
// Hop2: out[b][o]  = sum_{ass-edges dst=OUT0+o} w * acc1[src][b]
// Only ass-edges landing on OUTPUT nodes matter (~52K of 891K).
//
// Strategy: fixed-capacity per-destination buckets filled in ONE pass with an
// atomic ticket per edge (degrees are Binomial-concentrated; caps have >8 sigma
// headroom). No histogram, no prefix scan. Hop kernels consume the buckets
// atomic-free and reset the counters so every launch sees identical state
// (deterministic across graph replays; globals are zero-initialized at load).

#define B      128
#define IN_F   256
#define N_ASS  4096
#define OUT_F  256
#define ASS0   256
#define OUT0   (IN_F + N_ASS)   // 4352
#define CAP1   96               // max in-degree of an assoc node (E[13], sd 3.5)
#define CAP2   448              // max in-degree of an output node (E[205], sd 14)

__device__ float2 g_b1[N_ASS * CAP1];   // {src*B as int-bits, w} per hop1 edge (3 MB)
__device__ float2 g_b2[OUT_F * CAP2];   // {src*B as int-bits, w} per hop2 edge (0.9 MB)
__device__ int    g_c1[N_ASS];          // bucket counters (zero at every launch entry)
__device__ int    g_c2[OUT_F];
__device__ float  g_xT[IN_F * B];       // x transposed [src][b] (128 KB)
__device__ float  g_acc1[N_ASS * B];    // assoc activations (2 MB, L2 resident)

// ---------------------------------------------------------------- build (1 pass)
__global__ void k_build(const float* __restrict__ x,
                        const int* __restrict__ in_src, const int* __restrict__ in_dst,
                        const float* __restrict__ in_w, int E_in,
                        const int* __restrict__ a_src, const int* __restrict__ a_dst,
                        const float* __restrict__ a_w, int E_ass) {
    int i  = blockIdx.x * blockDim.x + threadIdx.x;
    int nt = gridDim.x * blockDim.x;

    // transpose x [B][IN_F] -> xT [IN_F][B]
    for (int idx = i; idx < IN_F * B; idx += nt) {
        int b = idx >> 8, s = idx & 255;               // IN_F == 256
        g_xT[s * B + b] = x[idx];
    }

    // hop1 edges (~52K): scalar scan
    for (int e = i; e < E_in; e += nt) {
        int d   = in_dst[e] - ASS0;
        int pos = atomicAdd(&g_c1[d], 1);
        g_b1[d * CAP1 + pos] = make_float2(__int_as_float(in_src[e] * B), in_w[e]);
    }

    // hop2 edges (~891K): int4-vectorized dst scan, filter dst >= OUT0 (~5.9%)
    int E4 = E_ass >> 2;
    const int4* a4 = (const int4*)a_dst;
    for (int q = i; q < E4; q += nt) {
        int4 d4 = a4[q];
        int  e  = q << 2;
        if (d4.x >= OUT0) { int d = d4.x - OUT0; int p = atomicAdd(&g_c2[d], 1);
            g_b2[d * CAP2 + p] = make_float2(__int_as_float((a_src[e    ] - ASS0) * B), a_w[e    ]); }
        if (d4.y >= OUT0) { int d = d4.y - OUT0; int p = atomicAdd(&g_c2[d], 1);
            g_b2[d * CAP2 + p] = make_float2(__int_as_float((a_src[e + 1] - ASS0) * B), a_w[e + 1]); }
        if (d4.z >= OUT0) { int d = d4.z - OUT0; int p = atomicAdd(&g_c2[d], 1);
            g_b2[d * CAP2 + p] = make_float2(__int_as_float((a_src[e + 2] - ASS0) * B), a_w[e + 2]); }
        if (d4.w >= OUT0) { int d = d4.w - OUT0; int p = atomicAdd(&g_c2[d], 1);
            g_b2[d * CAP2 + p] = make_float2(__int_as_float((a_src[e + 3] - ASS0) * B), a_w[e + 3]); }
    }
    for (int e = (E4 << 2) + i; e < E_ass; e += nt) {  // tail
        int d = a_dst[e];
        if (d >= OUT0) { int dd = d - OUT0; int p = atomicAdd(&g_c2[dd], 1);
            g_b2[dd * CAP2 + p] = make_float2(__int_as_float((a_src[e] - ASS0) * B), a_w[e]); }
    }
}

// ---------------------------------------------------------------- hop 1
// one block per assoc node, one thread per batch element; atomic-free
__global__ void k_hop1() {
    int j = blockIdx.x, b = threadIdx.x;
    __shared__ int sn;
    if (b == 0) { sn = g_c1[j]; g_c1[j] = 0; }         // consume + reset for next launch
    __syncthreads();
    int n = sn;
    const float2* bk = &g_b1[j * CAP1];
    float r = 0.f;
    int e = 0;
    for (; e + 4 <= n; e += 4) {
        float2 p0 = bk[e], p1 = bk[e + 1], p2 = bk[e + 2], p3 = bk[e + 3];
        r += p0.y * g_xT[__float_as_int(p0.x) + b];
        r += p1.y * g_xT[__float_as_int(p1.x) + b];
        r += p2.y * g_xT[__float_as_int(p2.x) + b];
        r += p3.y * g_xT[__float_as_int(p3.x) + b];
    }
    for (; e < n; e++) { float2 p = bk[e]; r += p.y * g_xT[__float_as_int(p.x) + b]; }
    g_acc1[j * B + b] = r;                             // coalesced, every row written
}

// ---------------------------------------------------------------- hop 2
// one block per output node, one thread per batch element; 8-wide unroll
__global__ void k_hop2(float* __restrict__ out) {
    int o = blockIdx.x, b = threadIdx.x;
    __shared__ int sn;
    if (b == 0) { sn = g_c2[o]; g_c2[o] = 0; }
    __syncthreads();
    int n = sn;
    const float2* bk = &g_b2[o * CAP2];
    float r = 0.f;
    int e = 0;
    for (; e + 8 <= n; e += 8) {
        float2 p[8];
#pragma unroll
        for (int k = 0; k < 8; k++) p[k] = bk[e + k];
#pragma unroll
        for (int k = 0; k < 8; k++) r += p[k].y * g_acc1[__float_as_int(p[k].x) + b];
    }
    for (; e < n; e++) { float2 p = bk[e]; r += p.y * g_acc1[__float_as_int(p.x) + b]; }
    out[b * OUT_F + o] = r;                            // [B, OUT_F], matches reference .T
}

// ---------------------------------------------------------------- launch
extern "C" void kernel_launch(void* const* d_in, const int* in_sizes, int n_in,
                              void* d_out, int out_size) {
    const float* x      = (const float*)d_in[0];
    const float* in_w   = (const float*)d_in[1];
    const float* a_w    = (const float*)d_in[2];
    const int*   in_src = (const int*)d_in[3];
    const int*   in_dst = (const int*)d_in[4];
    const int*   a_src  = (const int*)d_in[5];
    const int*   a_dst  = (const int*)d_in[6];
    int E_in  = in_sizes[1];
    int E_ass = in_sizes[2];
    float* out = (float*)d_out;

    k_build<<<512, 256>>>(x, in_src, in_dst, in_w, E_in, a_src, a_dst, a_w, E_ass);
    k_hop1 <<<N_ASS, B>>>();
    k_hop2 <<<OUT_F, B>>>(out);
}